// round 8
// baseline (speedup 1.0000x reference)
#include <cuda_runtime.h>
#include <math.h>

#define H 256
#define MAXE 500000
#define MAXG 256
#define FRONTIER_BONUS 0.5f
#define LN_EPS 1e-5f
#define F32_EPS 1.1920929e-07f
#define LOG_EPS -15.942385152878742f   // ln(2^-23)
#define NBLK_P1 1184
#define STOPG 4

// ---------------- device scratch (single memset-able struct) ----------------
// __align__(16) REQUIRED: float4 (LDG.128) access to w_att and S.
struct __align__(16) Scratch {
    float    S[MAXG * H];     // segment sums of edge_tokens
    float    w_att[H];        // att_vec @ W_edge  (atomic partials)
    float    w_q[H];          // att_vec @ W_query (atomic partials)
    unsigned maxenc[MAXG];    // order-preserving-uint segment max (0 == -inf)
};
__device__ Scratch g_z;
__device__ float g_qatt[MAXG];     // fully overwritten each run
__device__ float g_att[MAXE];      // fully overwritten each run
__device__ int   g_seg[MAXG + 1];  // segment bounds (fully overwritten)

// order-preserving float <-> uint; memset-0 acts as -infinity identity
__device__ __forceinline__ unsigned fenc(float f) {
    unsigned u = (unsigned)__float_as_int(f);
    return (u & 0x80000000u) ? ~u : (u | 0x80000000u);
}
__device__ __forceinline__ float fdec(unsigned u) {
    unsigned v = (u & 0x80000000u) ? (u & 0x7FFFFFFFu) : ~u;
    return __int_as_float((int)v);
}

// ------- setup: w_att/w_q partials (blocks 0-31) + segment bounds (32-33) --
__global__ void __launch_bounds__(256) prew_k(const float* __restrict__ W_edge,
                       const float* __restrict__ W_query,
                       const float* __restrict__ att_vec,
                       const int* __restrict__ batch, int E, int G) {
    int b = blockIdx.x, t = threadIdx.x;
    if (b < 32) {
        int m = b >> 4;                   // 0: W_edge, 1: W_query
        int c = b & 15;                   // row chunk of 16
        const float* W = m ? W_query : W_edge;
        int i0 = c * 16;
        float s = 0.f;
        #pragma unroll
        for (int i = 0; i < 16; i++)
            s = fmaf(__ldg(att_vec + i0 + i), __ldg(W + (i0 + i) * H + t), s);
        atomicAdd((m ? g_z.w_q : g_z.w_att) + t, s);
    } else {
        int i = (b - 32) * 256 + t;
        if (i > G) return;
        int lo = 0, hi = E;
        while (lo < hi) {
            int mid = (lo + hi) >> 1;
            if (__ldg(batch + mid) < i) lo = mid + 1; else hi = mid;
        }
        g_seg[i] = lo;
    }
}

// ---------------- qatt[g] = question_tokens[g] . w_q ----------------
__global__ void __launch_bounds__(256) qatt_k(const float* __restrict__ qtok, int G) {
    int w = threadIdx.x >> 5, l = threadIdx.x & 31;
    int g = blockIdx.x * 8 + w;
    if (g >= G) return;
    float s = 0.f;
    #pragma unroll
    for (int k = 0; k < 8; k++) {
        int j = l + 32 * k;
        s = fmaf(qtok[(size_t)g * H + j], g_z.w_q[j], s);
    }
    #pragma unroll
    for (int sh = 16; sh; sh >>= 1) s += __shfl_xor_sync(0xFFFFFFFFu, s, sh);
    if (l == 0) g_qatt[g] = s;
}

// ---------------- main streaming pass: warp-per-edge, x4 unroll ----------
struct RunState {
    float4 a0, a1;
    float rmax, qcur;
    int cur;
};

__device__ __forceinline__ void flush_run(RunState& st, int l) {
    if (st.cur < 0) return;
    float* Sp = &g_z.S[st.cur * H];
    atomicAdd(Sp + 4 * l + 0, st.a0.x);
    atomicAdd(Sp + 4 * l + 1, st.a0.y);
    atomicAdd(Sp + 4 * l + 2, st.a0.z);
    atomicAdd(Sp + 4 * l + 3, st.a0.w);
    atomicAdd(Sp + 128 + 4 * l + 0, st.a1.x);
    atomicAdd(Sp + 128 + 4 * l + 1, st.a1.y);
    atomicAdd(Sp + 128 + 4 * l + 2, st.a1.z);
    atomicAdd(Sp + 128 + 4 * l + 3, st.a1.w);
    if (l == 0) atomicMax(&g_z.maxenc[st.cur], fenc(st.rmax));
}

__device__ __forceinline__ void process_edge(RunState& st, int g, int selv,
                                             float4 x0, float4 x1,
                                             float4 wa0, float4 wa1,
                                             int e, int l) {
    if (g != st.cur) {
        flush_run(st, l);
        st.a0 = make_float4(0.f, 0.f, 0.f, 0.f);
        st.a1 = make_float4(0.f, 0.f, 0.f, 0.f);
        st.rmax = -INFINITY; st.cur = g;
        st.qcur = g_qatt[g];
    }
    st.a0.x += x0.x; st.a0.y += x0.y; st.a0.z += x0.z; st.a0.w += x0.w;
    st.a1.x += x1.x; st.a1.y += x1.y; st.a1.z += x1.z; st.a1.w += x1.w;
    float d = x0.x * wa0.x + x0.y * wa0.y + x0.z * wa0.z + x0.w * wa0.w
            + x1.x * wa1.x + x1.y * wa1.y + x1.z * wa1.z + x1.w * wa1.w;
    #pragma unroll
    for (int sh = 16; sh; sh >>= 1) d += __shfl_xor_sync(0xFFFFFFFFu, d, sh);
    float r = d + st.qcur;
    r = r > 0.f ? r : 0.2f * r;                       // LeakyReLU(0.2)
    if (selv == 0) r += FRONTIER_BONUS;               // candidate == frontier
    if (l == 0) g_att[e] = r;
    st.rmax = fmaxf(st.rmax, r);
}

__global__ void __launch_bounds__(256) pass1_k(const float* __restrict__ x,
                        const int* __restrict__ batch,
                        const int* __restrict__ sel,
                        int E) {
    int chunk = (E + NBLK_P1 - 1) / NBLK_P1;
    int lo = blockIdx.x * chunk;
    int hi = min(E, lo + chunk);
    int w = threadIdx.x >> 5, l = threadIdx.x & 31;

    const float4* wav = (const float4*)g_z.w_att;
    float4 wa0 = wav[l];
    float4 wa1 = wav[32 + l];

    RunState st;
    st.a0 = make_float4(0.f, 0.f, 0.f, 0.f);
    st.a1 = make_float4(0.f, 0.f, 0.f, 0.f);
    st.cur = -1; st.rmax = -INFINITY; st.qcur = 0.f;

    int e = lo + w;
    // x4 unroll: all loads unconditional and front-batched (8 LDG.128 in flight)
    for (; e + 24 < hi; e += 32) {
        int e1 = e + 8, e2 = e + 16, e3 = e + 24;
        int g0 = __ldg(batch + e);
        int g1 = __ldg(batch + e1);
        int g2 = __ldg(batch + e2);
        int g3 = __ldg(batch + e3);
        int s0 = __ldg(sel + e);
        int s1 = __ldg(sel + e1);
        int s2 = __ldg(sel + e2);
        int s3 = __ldg(sel + e3);
        const float4* r0 = (const float4*)(x + (size_t)e  * H);
        const float4* r1 = (const float4*)(x + (size_t)e1 * H);
        const float4* r2 = (const float4*)(x + (size_t)e2 * H);
        const float4* r3 = (const float4*)(x + (size_t)e3 * H);
        float4 xa0 = __ldg(r0 + l), xa1 = __ldg(r0 + 32 + l);
        float4 xb0 = __ldg(r1 + l), xb1 = __ldg(r1 + 32 + l);
        float4 xc0 = __ldg(r2 + l), xc1 = __ldg(r2 + 32 + l);
        float4 xd0 = __ldg(r3 + l), xd1 = __ldg(r3 + 32 + l);
        process_edge(st, g0, s0, xa0, xa1, wa0, wa1, e,  l);
        process_edge(st, g1, s1, xb0, xb1, wa0, wa1, e1, l);
        process_edge(st, g2, s2, xc0, xc1, wa0, wa1, e2, l);
        process_edge(st, g3, s3, xd0, xd1, wa0, wa1, e3, l);
    }
    for (; e < hi; e += 8) {
        int g = __ldg(batch + e);
        int s = __ldg(sel + e);
        const float4* row = (const float4*)(x + (size_t)e * H);
        float4 x0 = __ldg(row + l);
        float4 x1 = __ldg(row + 32 + l);
        process_edge(st, g, s, x0, x1, wa0, wa1, e, l);
    }
    flush_run(st, l);
}

// ---------------- fused post: softmax (blocks [0,G)) + stop head (4 g/block)
__device__ __forceinline__ void block_sum4(float v[STOPG], float4* red4, float out[STOPG]) {
    int l = threadIdx.x & 31, w = threadIdx.x >> 5;
    #pragma unroll
    for (int sh = 16; sh; sh >>= 1) {
        #pragma unroll
        for (int gg = 0; gg < STOPG; gg++)
            v[gg] += __shfl_xor_sync(0xFFFFFFFFu, v[gg], sh);
    }
    if (l == 0) red4[w] = make_float4(v[0], v[1], v[2], v[3]);
    __syncthreads();
    if (w == 0) {
        float4 xv = (l < 8) ? red4[l] : make_float4(0.f, 0.f, 0.f, 0.f);
        #pragma unroll
        for (int sh = 4; sh; sh >>= 1) {
            xv.x += __shfl_xor_sync(0xFFFFFFFFu, xv.x, sh);
            xv.y += __shfl_xor_sync(0xFFFFFFFFu, xv.y, sh);
            xv.z += __shfl_xor_sync(0xFFFFFFFFu, xv.z, sh);
            xv.w += __shfl_xor_sync(0xFFFFFFFFu, xv.w, sh);
        }
        if (l == 0) red4[0] = xv;
    }
    __syncthreads();
    float4 r = red4[0];
    out[0] = r.x; out[1] = r.y; out[2] = r.z; out[3] = r.w;
    __syncthreads();
}

__global__ void __launch_bounds__(256) post_k(
        const int* __restrict__ sel,
        const float* __restrict__ qtok, const float* __restrict__ W_edge,
        const float* __restrict__ ln_g, const float* __restrict__ ln_b,
        const float* __restrict__ W1, const float* __restrict__ b1,
        const float* __restrict__ W2, const float* __restrict__ b2,
        float* __restrict__ out_edge, float* __restrict__ out_stop,
        float* __restrict__ out_pooled, int E, int G) {
    int t = threadIdx.x;
    int l = t & 31, w = t >> 5;

    if (blockIdx.x < (unsigned)G) {
        // -------- segment softmax + edge logits --------
        __shared__ float red[32];
        __shared__ float s_lsum;
        int g = blockIdx.x;
        int lo = __ldg(g_seg + g);
        int hi = __ldg(g_seg + g + 1);
        if (lo >= hi) return;

        float m = fdec(g_z.maxenc[g]);
        float s = 0.f;
        for (int e = lo + t; e < hi; e += 256)
            if (__ldg(sel + e) == 0) s += __expf(__ldg(g_att + e) - m);
        #pragma unroll
        for (int sh = 16; sh; sh >>= 1) s += __shfl_xor_sync(0xFFFFFFFFu, s, sh);
        if (l == 0) red[w] = s;
        __syncthreads();
        if (w == 0) {
            float v = (l < 8) ? red[l] : 0.f;
            #pragma unroll
            for (int sh = 4; sh; sh >>= 1) v += __shfl_xor_sync(0xFFFFFFFFu, v, sh);
            if (l == 0) s_lsum = __logf(fmaxf(v, F32_EPS));
        }
        __syncthreads();
        float lsum = s_lsum;
        // log(max(p,eps)) = max(log p, log eps); log p = (att-m) - lsum
        for (int e = lo + t; e < hi; e += 256) {
            float o = LOG_EPS;
            if (__ldg(sel + e) == 0)
                o = fmaxf(__ldg(g_att + e) - m - lsum, LOG_EPS);
            out_edge[e] = o;
        }
    } else {
        // -------- stop head: STOPG graphs per block, half-warp per row ----
        __shared__ __align__(16) float ssh[STOPG][H];       // S rows
        __shared__ __align__(16) float psh[STOPG][H];       // matvec results
        __shared__ __align__(16) float xsh[STOPG][2 * H];   // layernormed inputs
        __shared__ float4 red4[32];
        int g0 = (blockIdx.x - G) * STOPG;
        int halfid = t >> 4, hl = t & 15;                   // 16 half-warps

        #pragma unroll
        for (int gg = 0; gg < STOPG; gg++) {
            int g = g0 + gg;
            ssh[gg][t] = (g < G) ? g_z.S[g * H + t] : 0.f;
        }
        __syncthreads();

        // matvec1: psh[gg][r] = S[gg] . W_edge[r,:]
        // half-warp owns row r; lanes read 4 consecutive-float4 strips (coalesced)
        for (int r = halfid; r < H; r += 16) {
            const float4* wr = (const float4*)(W_edge + (size_t)r * H);
            float4 w0 = __ldg(wr + hl),      w1 = __ldg(wr + hl + 16);
            float4 w2 = __ldg(wr + hl + 32), w3 = __ldg(wr + hl + 48);
            float p[STOPG];
            #pragma unroll
            for (int gg = 0; gg < STOPG; gg++) {
                const float4* s4 = (const float4*)ssh[gg];
                float4 a = s4[hl], b = s4[hl + 16], c = s4[hl + 32], d = s4[hl + 48];
                p[gg] = w0.x * a.x + w0.y * a.y + w0.z * a.z + w0.w * a.w
                      + w1.x * b.x + w1.y * b.y + w1.z * b.z + w1.w * b.w
                      + w2.x * c.x + w2.y * c.y + w2.z * c.z + w2.w * c.w
                      + w3.x * d.x + w3.y * d.y + w3.z * d.z + w3.w * d.w;
            }
            #pragma unroll
            for (int sh = 8; sh; sh >>= 1) {
                #pragma unroll
                for (int gg = 0; gg < STOPG; gg++)
                    p[gg] += __shfl_xor_sync(0xFFFFFFFFu, p[gg], sh);
            }
            if (hl == 0) {
                #pragma unroll
                for (int gg = 0; gg < STOPG; gg++) psh[gg][r] = p[gg];
            }
        }
        __syncthreads();

        float pe[STOPG], qv[STOPG];
        #pragma unroll
        for (int gg = 0; gg < STOPG; gg++) {
            int g = g0 + gg;
            float denom = 1.0f;
            if (g < G) {
                int c = __ldg(g_seg + g + 1) - __ldg(g_seg + g);
                denom = fmaxf((float)c, 1.0f);
            }
            pe[gg] = psh[gg][t] / denom;
            qv[gg] = (g < G) ? qtok[(size_t)g * H + t] : 0.f;
            if (g < G) out_pooled[(size_t)g * H + t] = pe[gg];
        }

        // LayerNorm over 512 per graph
        float v[STOPG], mu[STOPG], var[STOPG];
        #pragma unroll
        for (int gg = 0; gg < STOPG; gg++) v[gg] = pe[gg] + qv[gg];
        block_sum4(v, red4, mu);
        float d0[STOPG], d1[STOPG];
        #pragma unroll
        for (int gg = 0; gg < STOPG; gg++) {
            mu[gg] *= (1.0f / (2 * H));
            d0[gg] = pe[gg] - mu[gg];
            d1[gg] = qv[gg] - mu[gg];
            v[gg] = d0[gg] * d0[gg] + d1[gg] * d1[gg];
        }
        block_sum4(v, red4, var);
        float lg0 = ln_g[t], lb0 = ln_b[t], lg1 = ln_g[H + t], lb1 = ln_b[H + t];
        #pragma unroll
        for (int gg = 0; gg < STOPG; gg++) {
            float rstd = rsqrtf(var[gg] * (1.0f / (2 * H)) + LN_EPS);
            xsh[gg][t]     = d0[gg] * rstd * lg0 + lb0;
            xsh[gg][H + t] = d1[gg] * rstd * lg1 + lb1;
        }
        __syncthreads();

        // matvec2: psh[gg][r] = gelu(xn[gg] . W1[r,:] + b1[r]) * W2[r]
        for (int r = halfid; r < H; r += 16) {
            float p[STOPG];
            #pragma unroll
            for (int gg = 0; gg < STOPG; gg++) p[gg] = 0.f;
            const float4* w1r = (const float4*)(W1 + (size_t)r * (2 * H));
            #pragma unroll
            for (int k = 0; k < 8; k++) {
                float4 wv = __ldg(w1r + hl + 16 * k);
                #pragma unroll
                for (int gg = 0; gg < STOPG; gg++) {
                    float4 xv = ((const float4*)xsh[gg])[hl + 16 * k];
                    p[gg] = fmaf(wv.x, xv.x, fmaf(wv.y, xv.y,
                            fmaf(wv.z, xv.z, fmaf(wv.w, xv.w, p[gg]))));
                }
            }
            #pragma unroll
            for (int sh = 8; sh; sh >>= 1) {
                #pragma unroll
                for (int gg = 0; gg < STOPG; gg++)
                    p[gg] += __shfl_xor_sync(0xFFFFFFFFu, p[gg], sh);
            }
            if (hl == 0) {
                float bb = __ldg(b1 + r), w2v = __ldg(W2 + r);
                #pragma unroll
                for (int gg = 0; gg < STOPG; gg++) {
                    float a1 = p[gg] + bb;
                    float h1 = 0.5f * a1 * (1.0f + erff(a1 * 0.70710678118654752f));
                    psh[gg][r] = h1 * w2v;
                }
            }
        }
        __syncthreads();

        #pragma unroll
        for (int gg = 0; gg < STOPG; gg++) v[gg] = psh[gg][t];
        float tot[STOPG];
        block_sum4(v, red4, tot);
        if (t == 0) {
            float bias = b2[0];
            #pragma unroll
            for (int gg = 0; gg < STOPG; gg++)
                if (g0 + gg < G) out_stop[g0 + gg] = tot[gg] + bias;
        }
    }
}

// ---------------- launch ----------------
extern "C" void kernel_launch(void* const* d_in, const int* in_sizes, int n_in,
                              void* d_out, int out_size) {
    const float* edge_tokens = (const float*)d_in[0];
    const float* qtok        = (const float*)d_in[1];
    const int*   batch       = (const int*)d_in[2];
    const int*   sel         = (const int*)d_in[3];
    const float* W_edge      = (const float*)d_in[4];
    const float* W_query     = (const float*)d_in[5];
    const float* att_vec     = (const float*)d_in[6];
    const float* ln_g        = (const float*)d_in[7];
    const float* ln_b        = (const float*)d_in[8];
    const float* W1          = (const float*)d_in[9];
    const float* b1          = (const float*)d_in[10];
    const float* W2          = (const float*)d_in[11];
    const float* b2          = (const float*)d_in[12];

    int E = in_sizes[0] / H;
    int G = in_sizes[1] / H;

    float* out = (float*)d_out;
    float* out_edge   = out;            // [E]
    float* out_stop   = out + E;        // [G]
    float* out_pooled = out + E + G;    // [G*H]

    void* zp = nullptr;
    cudaGetSymbolAddress(&zp, g_z);
    cudaMemsetAsync(zp, 0, sizeof(Scratch));

    prew_k<<<34, 256>>>(W_edge, W_query, att_vec, batch, E, G);
    qatt_k<<<(G + 7) / 8, 256>>>(qtok, G);
    pass1_k<<<NBLK_P1, 256>>>(edge_tokens, batch, sel, E);
    post_k<<<G + (G + STOPG - 1) / STOPG, 256>>>(
        sel, qtok, W_edge, ln_g, ln_b, W1, b1, W2, b2,
        out_edge, out_stop, out_pooled, E, G);
}

// round 9
// speedup vs baseline: 1.0193x; 1.0193x over previous
#include <cuda_runtime.h>
#include <math.h>

#define H 256
#define MAXE 500000
#define MAXG 256
#define FRONTIER_BONUS 0.5f
#define LN_EPS 1e-5f
#define F32_EPS 1.1920929e-07f
#define LOG_EPS -15.942385152878742f   // ln(2^-23)
#define NBLK_P1 1184
#define PG 4                            // graphs per stop-head block

// ---------------- device scratch (single memset-able struct) ----------------
// __align__(16) REQUIRED: float4 (LDG.128) access to w_att and S.
struct __align__(16) Scratch {
    float    S[MAXG * H];     // segment sums of edge_tokens
    float    w_att[H];        // att_vec @ W_edge  (atomic partials)
    float    w_q[H];          // att_vec @ W_query (atomic partials)
    unsigned maxenc[MAXG];    // order-preserving-uint segment max (0 == -inf)
};
__device__ Scratch g_z;
__device__ float g_qatt[MAXG];            // fully overwritten each run
__device__ float g_att[MAXE];             // fully overwritten each run
__device__ int   g_seg[MAXG + 1];         // segment bounds (fully overwritten)
__device__ __align__(16) float g_xn[MAXG * 2 * H];  // layernormed stop input

// order-preserving float <-> uint; memset-0 acts as -infinity identity
__device__ __forceinline__ unsigned fenc(float f) {
    unsigned u = (unsigned)__float_as_int(f);
    return (u & 0x80000000u) ? ~u : (u | 0x80000000u);
}
__device__ __forceinline__ float fdec(unsigned u) {
    unsigned v = (u & 0x80000000u) ? (u & 0x7FFFFFFFu) : ~u;
    return __int_as_float((int)v);
}

// ------- setup: w_att/w_q partials (blocks 0-31) + segment bounds (32-33) --
__global__ void __launch_bounds__(256) prew_k(const float* __restrict__ W_edge,
                       const float* __restrict__ W_query,
                       const float* __restrict__ att_vec,
                       const int* __restrict__ batch, int E, int G) {
    int b = blockIdx.x, t = threadIdx.x;
    if (b < 32) {
        int m = b >> 4;                   // 0: W_edge, 1: W_query
        int c = b & 15;                   // row chunk of 16
        const float* W = m ? W_query : W_edge;
        int i0 = c * 16;
        float s = 0.f;
        #pragma unroll
        for (int i = 0; i < 16; i++)
            s = fmaf(__ldg(att_vec + i0 + i), __ldg(W + (i0 + i) * H + t), s);
        atomicAdd((m ? g_z.w_q : g_z.w_att) + t, s);
    } else {
        int i = (b - 32) * 256 + t;
        if (i > G) return;
        int lo = 0, hi = E;
        while (lo < hi) {
            int mid = (lo + hi) >> 1;
            if (__ldg(batch + mid) < i) lo = mid + 1; else hi = mid;
        }
        g_seg[i] = lo;
    }
}

// ---------------- qatt[g] = question_tokens[g] . w_q ----------------
__global__ void __launch_bounds__(256) qatt_k(const float* __restrict__ qtok, int G) {
    int w = threadIdx.x >> 5, l = threadIdx.x & 31;
    int g = blockIdx.x * 8 + w;
    if (g >= G) return;
    float s = 0.f;
    #pragma unroll
    for (int k = 0; k < 8; k++) {
        int j = l + 32 * k;
        s = fmaf(qtok[(size_t)g * H + j], g_z.w_q[j], s);
    }
    #pragma unroll
    for (int sh = 16; sh; sh >>= 1) s += __shfl_xor_sync(0xFFFFFFFFu, s, sh);
    if (l == 0) g_qatt[g] = s;
}

// ---------------- main streaming pass: warp-per-edge, x4 unroll ----------
struct RunState {
    float4 a0, a1;
    float rmax, qcur;
    int cur;
};

__device__ __forceinline__ void flush_run(RunState& st, int l) {
    if (st.cur < 0) return;
    float* Sp = &g_z.S[st.cur * H];
    atomicAdd(Sp + 4 * l + 0, st.a0.x);
    atomicAdd(Sp + 4 * l + 1, st.a0.y);
    atomicAdd(Sp + 4 * l + 2, st.a0.z);
    atomicAdd(Sp + 4 * l + 3, st.a0.w);
    atomicAdd(Sp + 128 + 4 * l + 0, st.a1.x);
    atomicAdd(Sp + 128 + 4 * l + 1, st.a1.y);
    atomicAdd(Sp + 128 + 4 * l + 2, st.a1.z);
    atomicAdd(Sp + 128 + 4 * l + 3, st.a1.w);
    if (l == 0) atomicMax(&g_z.maxenc[st.cur], fenc(st.rmax));
}

__device__ __forceinline__ void process_edge(RunState& st, int g, int selv,
                                             float4 x0, float4 x1,
                                             float4 wa0, float4 wa1,
                                             int e, int l) {
    if (g != st.cur) {
        flush_run(st, l);
        st.a0 = make_float4(0.f, 0.f, 0.f, 0.f);
        st.a1 = make_float4(0.f, 0.f, 0.f, 0.f);
        st.rmax = -INFINITY; st.cur = g;
        st.qcur = g_qatt[g];
    }
    st.a0.x += x0.x; st.a0.y += x0.y; st.a0.z += x0.z; st.a0.w += x0.w;
    st.a1.x += x1.x; st.a1.y += x1.y; st.a1.z += x1.z; st.a1.w += x1.w;
    float d = x0.x * wa0.x + x0.y * wa0.y + x0.z * wa0.z + x0.w * wa0.w
            + x1.x * wa1.x + x1.y * wa1.y + x1.z * wa1.z + x1.w * wa1.w;
    #pragma unroll
    for (int sh = 16; sh; sh >>= 1) d += __shfl_xor_sync(0xFFFFFFFFu, d, sh);
    float r = d + st.qcur;
    r = r > 0.f ? r : 0.2f * r;                       // LeakyReLU(0.2)
    if (selv == 0) r += FRONTIER_BONUS;               // candidate == frontier
    if (l == 0) g_att[e] = r;
    st.rmax = fmaxf(st.rmax, r);
}

__global__ void __launch_bounds__(256) pass1_k(const float* __restrict__ x,
                        const int* __restrict__ batch,
                        const int* __restrict__ sel,
                        int E) {
    int chunk = (E + NBLK_P1 - 1) / NBLK_P1;
    int lo = blockIdx.x * chunk;
    int hi = min(E, lo + chunk);
    int w = threadIdx.x >> 5, l = threadIdx.x & 31;

    const float4* wav = (const float4*)g_z.w_att;
    float4 wa0 = wav[l];
    float4 wa1 = wav[32 + l];

    RunState st;
    st.a0 = make_float4(0.f, 0.f, 0.f, 0.f);
    st.a1 = make_float4(0.f, 0.f, 0.f, 0.f);
    st.cur = -1; st.rmax = -INFINITY; st.qcur = 0.f;

    int e = lo + w;
    // x4 unroll: all loads unconditional and front-batched (8 LDG.128 in flight)
    for (; e + 24 < hi; e += 32) {
        int e1 = e + 8, e2 = e + 16, e3 = e + 24;
        int g0 = __ldg(batch + e);
        int g1 = __ldg(batch + e1);
        int g2 = __ldg(batch + e2);
        int g3 = __ldg(batch + e3);
        int s0 = __ldg(sel + e);
        int s1 = __ldg(sel + e1);
        int s2 = __ldg(sel + e2);
        int s3 = __ldg(sel + e3);
        const float4* r0 = (const float4*)(x + (size_t)e  * H);
        const float4* r1 = (const float4*)(x + (size_t)e1 * H);
        const float4* r2 = (const float4*)(x + (size_t)e2 * H);
        const float4* r3 = (const float4*)(x + (size_t)e3 * H);
        float4 xa0 = __ldg(r0 + l), xa1 = __ldg(r0 + 32 + l);
        float4 xb0 = __ldg(r1 + l), xb1 = __ldg(r1 + 32 + l);
        float4 xc0 = __ldg(r2 + l), xc1 = __ldg(r2 + 32 + l);
        float4 xd0 = __ldg(r3 + l), xd1 = __ldg(r3 + 32 + l);
        process_edge(st, g0, s0, xa0, xa1, wa0, wa1, e,  l);
        process_edge(st, g1, s1, xb0, xb1, wa0, wa1, e1, l);
        process_edge(st, g2, s2, xc0, xc1, wa0, wa1, e2, l);
        process_edge(st, g3, s3, xd0, xd1, wa0, wa1, e3, l);
    }
    for (; e < hi; e += 8) {
        int g = __ldg(batch + e);
        int s = __ldg(sel + e);
        const float4* row = (const float4*)(x + (size_t)e * H);
        float4 x0 = __ldg(row + l);
        float4 x1 = __ldg(row + 32 + l);
        process_edge(st, g, s, x0, x1, wa0, wa1, e, l);
    }
    flush_run(st, l);
}

// ---------------- segment softmax + edge logits (block per graph) ---------
__global__ void __launch_bounds__(256) softmax_k(const int* __restrict__ sel,
                          float* __restrict__ out_edge, int E, int G) {
    __shared__ float red[32];
    __shared__ float s_lsum;
    int t = threadIdx.x, l = t & 31, w = t >> 5;
    int g = blockIdx.x;
    int lo = __ldg(g_seg + g);
    int hi = __ldg(g_seg + g + 1);
    if (lo >= hi) return;

    float m = fdec(g_z.maxenc[g]);
    float s = 0.f;
    for (int e = lo + t; e < hi; e += 256)
        if (__ldg(sel + e) == 0) s += __expf(__ldg(g_att + e) - m);
    #pragma unroll
    for (int sh = 16; sh; sh >>= 1) s += __shfl_xor_sync(0xFFFFFFFFu, s, sh);
    if (l == 0) red[w] = s;
    __syncthreads();
    if (w == 0) {
        float v = (l < 8) ? red[l] : 0.f;
        #pragma unroll
        for (int sh = 4; sh; sh >>= 1) v += __shfl_xor_sync(0xFFFFFFFFu, v, sh);
        if (l == 0) s_lsum = __logf(fmaxf(v, F32_EPS));
    }
    __syncthreads();
    float lsum = s_lsum;
    // log(max(p,eps)) = max(log p, log eps); log p = (att-m) - lsum
    for (int e = lo + t; e < hi; e += 256) {
        float o = LOG_EPS;
        if (__ldg(sel + e) == 0)
            o = fmaxf(__ldg(g_att + e) - m - lsum, LOG_EPS);
        out_edge[e] = o;
    }
}

// ------- pooled matvec + LayerNorm (PG graphs/block, warp-per-row) --------
__device__ __forceinline__ void block_sum4(float v[PG], float4* red4, float out[PG]) {
    int l = threadIdx.x & 31, w = threadIdx.x >> 5;
    #pragma unroll
    for (int sh = 16; sh; sh >>= 1) {
        #pragma unroll
        for (int gg = 0; gg < PG; gg++)
            v[gg] += __shfl_xor_sync(0xFFFFFFFFu, v[gg], sh);
    }
    if (l == 0) red4[w] = make_float4(v[0], v[1], v[2], v[3]);
    __syncthreads();
    if (w == 0) {
        float4 xv = (l < 8) ? red4[l] : make_float4(0.f, 0.f, 0.f, 0.f);
        #pragma unroll
        for (int sh = 4; sh; sh >>= 1) {
            xv.x += __shfl_xor_sync(0xFFFFFFFFu, xv.x, sh);
            xv.y += __shfl_xor_sync(0xFFFFFFFFu, xv.y, sh);
            xv.z += __shfl_xor_sync(0xFFFFFFFFu, xv.z, sh);
            xv.w += __shfl_xor_sync(0xFFFFFFFFu, xv.w, sh);
        }
        if (l == 0) red4[0] = xv;
    }
    __syncthreads();
    float4 r = red4[0];
    out[0] = r.x; out[1] = r.y; out[2] = r.z; out[3] = r.w;
    __syncthreads();
}

__global__ void __launch_bounds__(256) pool_ln_k(
        const float* __restrict__ qtok, const float* __restrict__ W_edge,
        const float* __restrict__ ln_g, const float* __restrict__ ln_b,
        float* __restrict__ out_pooled, int G) {
    __shared__ __align__(16) float ssh[PG][H];   // S/denom
    __shared__ __align__(16) float psh[PG][H];   // pooled
    __shared__ float4 red4[32];
    int t = threadIdx.x, l = t & 31, w = t >> 5;
    int g0 = blockIdx.x * PG;

    #pragma unroll
    for (int gg = 0; gg < PG; gg++) {
        int g = g0 + gg;
        float v = 0.f;
        if (g < G) {
            int c = __ldg(g_seg + g + 1) - __ldg(g_seg + g);
            v = g_z.S[g * H + t] / fmaxf((float)c, 1.0f);
        }
        ssh[gg][t] = v;
    }
    __syncthreads();

    // warp w owns rows [w*32, w*32+32): lane reads wr[l], wr[l+32] (coalesced),
    // 32 independent rows per warp -> 64 loads in flight
    for (int r = w * 32; r < w * 32 + 32; r++) {
        const float4* wr = (const float4*)(W_edge + (size_t)r * H);
        float4 wa = __ldg(wr + l);
        float4 wb = __ldg(wr + 32 + l);
        float p[PG];
        #pragma unroll
        for (int gg = 0; gg < PG; gg++) {
            const float4* s4 = (const float4*)ssh[gg];
            float4 a = s4[l], b = s4[32 + l];
            p[gg] = wa.x * a.x + wa.y * a.y + wa.z * a.z + wa.w * a.w
                  + wb.x * b.x + wb.y * b.y + wb.z * b.z + wb.w * b.w;
        }
        #pragma unroll
        for (int sh = 16; sh; sh >>= 1) {
            #pragma unroll
            for (int gg = 0; gg < PG; gg++)
                p[gg] += __shfl_xor_sync(0xFFFFFFFFu, p[gg], sh);
        }
        if (l == 0) {
            #pragma unroll
            for (int gg = 0; gg < PG; gg++) psh[gg][r] = p[gg];
        }
    }
    __syncthreads();

    float pe[PG], qv[PG];
    #pragma unroll
    for (int gg = 0; gg < PG; gg++) {
        int g = g0 + gg;
        pe[gg] = psh[gg][t];
        qv[gg] = (g < G) ? qtok[(size_t)g * H + t] : 0.f;
        if (g < G) out_pooled[(size_t)g * H + t] = pe[gg];
    }

    float v[PG], mu[PG], var[PG];
    #pragma unroll
    for (int gg = 0; gg < PG; gg++) v[gg] = pe[gg] + qv[gg];
    block_sum4(v, red4, mu);
    float d0[PG], d1[PG];
    #pragma unroll
    for (int gg = 0; gg < PG; gg++) {
        mu[gg] *= (1.0f / (2 * H));
        d0[gg] = pe[gg] - mu[gg];
        d1[gg] = qv[gg] - mu[gg];
        v[gg] = d0[gg] * d0[gg] + d1[gg] * d1[gg];
    }
    block_sum4(v, red4, var);
    float lg0 = ln_g[t], lb0 = ln_b[t], lg1 = ln_g[H + t], lb1 = ln_b[H + t];
    #pragma unroll
    for (int gg = 0; gg < PG; gg++) {
        int g = g0 + gg;
        if (g >= G) continue;
        float rstd = rsqrtf(var[gg] * (1.0f / (2 * H)) + LN_EPS);
        g_xn[(size_t)g * 2 * H + t]     = d0[gg] * rstd * lg0 + lb0;
        g_xn[(size_t)g * 2 * H + H + t] = d1[gg] * rstd * lg1 + lb1;
    }
}

// ------- MLP: gelu(xn @ W1.T + b1) . W2 + b2 (PG graphs/block) ------------
__global__ void __launch_bounds__(256) mlp_k(
        const float* __restrict__ W1, const float* __restrict__ b1,
        const float* __restrict__ W2, const float* __restrict__ b2,
        float* __restrict__ out_stop, int G) {
    __shared__ __align__(16) float xsh[PG][2 * H];
    __shared__ float4 red4[32];
    int t = threadIdx.x, l = t & 31, w = t >> 5;
    int g0 = blockIdx.x * PG;

    #pragma unroll
    for (int gg = 0; gg < PG; gg++) {
        int g = g0 + gg;
        xsh[gg][t]     = (g < G) ? g_xn[(size_t)g * 2 * H + t] : 0.f;
        xsh[gg][H + t] = (g < G) ? g_xn[(size_t)g * 2 * H + H + t] : 0.f;
    }
    __syncthreads();

    float acc[PG];
    #pragma unroll
    for (int gg = 0; gg < PG; gg++) acc[gg] = 0.f;

    // warp w owns rows [w*32, w*32+32): lane reads 4 coalesced float4 strips
    for (int r = w * 32; r < w * 32 + 32; r++) {
        const float4* w1r = (const float4*)(W1 + (size_t)r * (2 * H));
        float4 w0 = __ldg(w1r + l),      w1v = __ldg(w1r + l + 32);
        float4 w2v = __ldg(w1r + l + 64), w3 = __ldg(w1r + l + 96);
        float p[PG];
        #pragma unroll
        for (int gg = 0; gg < PG; gg++) {
            const float4* x4 = (const float4*)xsh[gg];
            float4 a = x4[l], b = x4[l + 32], c = x4[l + 64], d = x4[l + 96];
            p[gg] = w0.x * a.x + w0.y * a.y + w0.z * a.z + w0.w * a.w
                  + w1v.x * b.x + w1v.y * b.y + w1v.z * b.z + w1v.w * b.w
                  + w2v.x * c.x + w2v.y * c.y + w2v.z * c.z + w2v.w * c.w
                  + w3.x * d.x + w3.y * d.y + w3.z * d.z + w3.w * d.w;
        }
        #pragma unroll
        for (int sh = 16; sh; sh >>= 1) {
            #pragma unroll
            for (int gg = 0; gg < PG; gg++)
                p[gg] += __shfl_xor_sync(0xFFFFFFFFu, p[gg], sh);
        }
        if (l == 0) {
            float bb = __ldg(b1 + r), wv = __ldg(W2 + r);
            #pragma unroll
            for (int gg = 0; gg < PG; gg++) {
                float a1 = p[gg] + bb;
                float h1 = 0.5f * a1 * (1.0f + erff(a1 * 0.70710678118654752f));
                acc[gg] = fmaf(h1, wv, acc[gg]);
            }
        }
    }
    // acc nonzero only on lane 0 of each warp; block reduction handles it
    float tot[PG];
    block_sum4(acc, red4, tot);
    if (t == 0) {
        float bias = b2[0];
        #pragma unroll
        for (int gg = 0; gg < PG; gg++)
            if (g0 + gg < G) out_stop[g0 + gg] = tot[gg] + bias;
    }
}

// ---------------- launch ----------------
extern "C" void kernel_launch(void* const* d_in, const int* in_sizes, int n_in,
                              void* d_out, int out_size) {
    const float* edge_tokens = (const float*)d_in[0];
    const float* qtok        = (const float*)d_in[1];
    const int*   batch       = (const int*)d_in[2];
    const int*   sel         = (const int*)d_in[3];
    const float* W_edge      = (const float*)d_in[4];
    const float* W_query     = (const float*)d_in[5];
    const float* att_vec     = (const float*)d_in[6];
    const float* ln_g        = (const float*)d_in[7];
    const float* ln_b        = (const float*)d_in[8];
    const float* W1          = (const float*)d_in[9];
    const float* b1          = (const float*)d_in[10];
    const float* W2          = (const float*)d_in[11];
    const float* b2          = (const float*)d_in[12];

    int E = in_sizes[0] / H;
    int G = in_sizes[1] / H;

    float* out = (float*)d_out;
    float* out_edge   = out;            // [E]
    float* out_stop   = out + E;        // [G]
    float* out_pooled = out + E + G;    // [G*H]

    void* zp = nullptr;
    cudaGetSymbolAddress(&zp, g_z);
    cudaMemsetAsync(zp, 0, sizeof(Scratch));

    int nstop = (G + PG - 1) / PG;
    prew_k<<<34, 256>>>(W_edge, W_query, att_vec, batch, E, G);
    qatt_k<<<(G + 7) / 8, 256>>>(qtok, G);
    pass1_k<<<NBLK_P1, 256>>>(edge_tokens, batch, sel, E);
    softmax_k<<<G, 256>>>(sel, out_edge, E, G);
    pool_ln_k<<<nstop, 256>>>(qtok, W_edge, ln_g, ln_b, out_pooled, G);
    mlp_k<<<nstop, 256>>>(W1, b1, W2, b2, out_stop, G);
}